// round 6
// baseline (speedup 1.0000x reference)
#include <cuda_runtime.h>

#define BB 1024
#define TT 2048
#define DD 16
#define UU 4
#define HH 128
#define MM 8
#define NT 512
#define INP 28          // sINt row pitch (floats)
#define H2P 132         // sH1 slice / sH2 / sW2T row pitch (floats)
#define W0P 24          // sW0T row pitch (floats)

typedef unsigned long long u64;

__device__ __forceinline__ u64 pk2(float lo, float hi) {
    u64 r; asm("mov.b64 %0, {%1, %2};" : "=l"(r) : "f"(lo), "f"(hi)); return r;
}
__device__ __forceinline__ void upk2(u64 v, float& lo, float& hi) {
    asm("mov.b64 {%0, %1}, %2;" : "=f"(lo), "=f"(hi) : "l"(v));
}
__device__ __forceinline__ u64 ffma2(u64 a, u64 b, u64 c) {
    u64 d; asm("fma.rn.f32x2 %0, %1, %2, %3;" : "=l"(d) : "l"(a), "l"(b), "l"(c)); return d;
}
__device__ __forceinline__ u64 add2(u64 a, u64 b) {
    u64 c; asm("add.rn.f32x2 %0, %1, %2;" : "=l"(c) : "l"(a), "l"(b)); return c;
}
__device__ __forceinline__ float tanh_fast(float x) {
    float y; asm("tanh.approx.f32 %0, %1;" : "=f"(y) : "f"(x)); return y;
}
__device__ __forceinline__ u64 shfl_xor64(u64 v, int mask) {
    unsigned lo = (unsigned)v, hi = (unsigned)(v >> 32);
    lo = __shfl_xor_sync(0xffffffffu, lo, mask);
    hi = __shfl_xor_sync(0xffffffffu, hi, mask);
    return ((u64)hi << 32) | (u64)lo;
}

__global__ void __launch_bounds__(NT, 1)
gnsde_kernel(const float* __restrict__ carry,
             const float* __restrict__ x,
             const float* __restrict__ noise,
             const float* __restrict__ W0,
             const float* __restrict__ b0,
             const float* __restrict__ W1,
             const float* __restrict__ b1,
             const float* __restrict__ W2,
             const float* __restrict__ b2,
             float* __restrict__ out)
{
    __shared__ __align__(16) float sW0T[HH * W0P];      // [j][k], pitch 24
    __shared__ __align__(16) float sW2T[DD * H2P];      // [d][k], pitch 132
    __shared__ __align__(16) float sH1[8 * H2P];        // [k>>4][ (k&15)*8 + m ]
    __shared__ __align__(16) float sH2[MM * H2P];       // [m][j]
    __shared__ __align__(16) float sINt[MM * INP];      // [m][k]: 0..15=y, 16..19=x_t

    const int tid = threadIdx.x;
    const int b0r = blockIdx.x * MM;

    // layer-0 identity: (j0, mp0)
    const int j0  = tid >> 2;
    const int mp0 = tid & 3;
    // layer-1 identity: (jp, kq)
    const int jp  = tid >> 3;
    const int kq  = tid & 7;
    // layer-2 identity: warp w covers md = 8w..8w+7; lane = pair*4 + kq2
    const int md2  = (tid >> 5) * 8 + ((tid & 31) >> 2);
    const int kq2  = tid & 3;
    const int m2   = md2 >> 4;
    const int d2   = md2 & 15;

    // ---- persistent registers: W1 slice pre-duplicated as f32x2 pairs ----
    u64 w1d0[16], w1d1[16];
#pragma unroll
    for (int kk = 0; kk < 16; ++kk) {
        float wa = W1[(kq * 16 + kk) * HH + 2 * jp];
        float wb = W1[(kq * 16 + kk) * HH + 2 * jp + 1];
        w1d0[kk] = pk2(wa, wa);
        w1d1[kk] = pk2(wb, wb);
    }
    const float b0j = b0[j0];
    const float b1v = b1[2 * jp + (kq >> 2)];
    const float b2v = b2[d2];
    float yreg = carry[(size_t)(b0r + m2) * DD + d2];   // live on kq2==0 lanes

    // ---- stage shared ----
    for (int idx = tid; idx < (DD + UU) * HH; idx += NT) {
        int k = idx >> 7, j = idx & 127;
        sW0T[j * W0P + k] = W0[idx];
    }
    for (int idx = tid; idx < HH * DD; idx += NT) {
        int i = idx >> 4, d = idx & 15;
        sW2T[d * H2P + i] = W2[idx];
    }
    if (kq2 == 0) sINt[m2 * INP + d2] = yreg;
    if (tid >= 504) {
        int m = tid - 504;
        float4 xv = *(const float4*)&x[((size_t)(b0r + m) * TT) * UU];
        *(float4*)&sINt[m * INP + DD] = xv;
    }
    __syncthreads();

    const float alpha = 0.1f;
    const float onema = 0.9f;
    const float sqa   = 0.31622776601683794f;

    float* ys  = out;
    float* mts = out + (size_t)BB * TT * DD;
    float* mus = out + 2ull * BB * TT * DD;

    for (int t = 0; t < TT; ++t) {
        // ---- prefetch globals ----
        float nz = 0.0f;
        if (kq2 == 0) nz = noise[((size_t)(b0r + m2) * TT + t) * DD + d2];
        float4 xn = make_float4(0.f, 0.f, 0.f, 0.f);
        const bool xp = (tid >= 504) && (t + 1 < TT);
        if (xp) xn = *(const float4*)&x[((size_t)(b0r + (tid - 504)) * TT + (t + 1)) * UU];

        // ===== layer 0: thread (j0, mp0); k-dot via f32x2 pairs =====
        {
            u64 aA0 = 0, aA1 = 0, aB0 = 0, aB1 = 0;
            const float* r0p = &sINt[(2 * mp0) * INP];
            const float* r1p = &sINt[(2 * mp0 + 1) * INP];
            const float* w0p = &sW0T[j0 * W0P];
#pragma unroll
            for (int i = 0; i < 5; ++i) {
                ulonglong2 wv = *(const ulonglong2*)&w0p[4 * i];   // (w4i,w4i+1),(w4i+2,w4i+3)
                ulonglong2 hA = *(const ulonglong2*)&r0p[4 * i];
                ulonglong2 hB = *(const ulonglong2*)&r1p[4 * i];
                aA0 = ffma2(wv.x, hA.x, aA0);
                aA1 = ffma2(wv.y, hA.y, aA1);
                aB0 = ffma2(wv.x, hB.x, aB0);
                aB1 = ffma2(wv.y, hB.y, aB1);
            }
            float lA, hA2; upk2(add2(aA0, aA1), lA, hA2);
            float lB, hB2; upk2(add2(aB0, aB1), lB, hB2);
            float v0 = tanh_fast(lA + hA2 + b0j);
            float v1 = tanh_fast(lB + hB2 + b0j);
            *(u64*)&sH1[(j0 >> 4) * H2P + (j0 & 15) * 8 + 2 * mp0] = pk2(v0, v1);
        }
        __syncthreads();

        // ===== layer 1: thread (jp, kq); pre-duplicated weights, 10 instr/kk =====
        {
            u64 a0 = 0, a1 = 0, a2 = 0, a3 = 0, a4 = 0, a5 = 0, a6 = 0, a7 = 0;
            const float* hbase = &sH1[kq * H2P];
#pragma unroll
            for (int kk = 0; kk < 16; ++kk) {
                ulonglong2 hA = *(const ulonglong2*)&hbase[kk * 8];
                ulonglong2 hB = *(const ulonglong2*)&hbase[kk * 8 + 4];
                a0 = ffma2(w1d0[kk], hA.x, a0); a1 = ffma2(w1d0[kk], hA.y, a1);
                a2 = ffma2(w1d0[kk], hB.x, a2); a3 = ffma2(w1d0[kk], hB.y, a3);
                a4 = ffma2(w1d1[kk], hA.x, a4); a5 = ffma2(w1d1[kk], hA.y, a5);
                a6 = ffma2(w1d1[kk], hB.x, a6); a7 = ffma2(w1d1[kk], hB.y, a7);
            }
            // index-halving butterfly over the 8-way k-split
            const bool u4 = (kq & 4) != 0;
            u64 k0 = u4 ? a4 : a0, s0 = u4 ? a0 : a4;
            u64 k1 = u4 ? a5 : a1, s1 = u4 ? a1 : a5;
            u64 k2 = u4 ? a6 : a2, s2 = u4 ? a2 : a6;
            u64 k3 = u4 ? a7 : a3, s3 = u4 ? a3 : a7;
            u64 n0 = add2(k0, shfl_xor64(s0, 4));
            u64 n1 = add2(k1, shfl_xor64(s1, 4));
            u64 n2 = add2(k2, shfl_xor64(s2, 4));
            u64 n3 = add2(k3, shfl_xor64(s3, 4));
            const bool u2 = (kq & 2) != 0;
            u64 p0k = u2 ? n2 : n0, p0s = u2 ? n0 : n2;
            u64 p1k = u2 ? n3 : n1, p1s = u2 ? n1 : n3;
            u64 p0 = add2(p0k, shfl_xor64(p0s, 2));
            u64 p1 = add2(p1k, shfl_xor64(p1s, 2));
            const bool u1 = (kq & 1) != 0;
            u64 qk = u1 ? p1 : p0, qs = u1 ? p0 : p1;
            u64 tot = add2(qk, shfl_xor64(qs, 1));

            float lo, hi; upk2(tot, lo, hi);
            lo = tanh_fast(lo + b1v);
            hi = tanh_fast(hi + b1v);
            const int jw = 2 * jp + (kq >> 2);
            const int mA = 2 * (kq & 3);
            sH2[mA * H2P + jw]       = lo;
            sH2[(mA + 1) * H2P + jw] = hi;
        }
        __syncthreads();

        // ===== layer 2 + gate: all 16 warps; lane = (pair, kq2) =====
        {
            u64 aA = 0, aB = 0;
            const float* hr = &sH2[m2 * H2P + kq2 * 32];
            const float* wr = &sW2T[d2 * H2P + kq2 * 32];
            {
                ulonglong2 h0 = *(const ulonglong2*)&hr[0];
                ulonglong2 w0v = *(const ulonglong2*)&wr[0];
                ulonglong2 h1 = *(const ulonglong2*)&hr[4];
                ulonglong2 w1v = *(const ulonglong2*)&wr[4];
                aA = ffma2(h0.x, w0v.x, aA); aB = ffma2(h0.y, w0v.y, aB);
                aA = ffma2(h1.x, w1v.x, aA); aB = ffma2(h1.y, w1v.y, aB);
                ulonglong2 h2v = *(const ulonglong2*)&hr[8];
                ulonglong2 w2v = *(const ulonglong2*)&wr[8];
                ulonglong2 h3 = *(const ulonglong2*)&hr[12];
                ulonglong2 w3v = *(const ulonglong2*)&wr[12];
                aA = ffma2(h2v.x, w2v.x, aA); aB = ffma2(h2v.y, w2v.y, aB);
                aA = ffma2(h3.x, w3v.x, aA); aB = ffma2(h3.y, w3v.y, aB);
                ulonglong2 h4 = *(const ulonglong2*)&hr[16];
                ulonglong2 w4v = *(const ulonglong2*)&wr[16];
                ulonglong2 h5 = *(const ulonglong2*)&hr[20];
                ulonglong2 w5v = *(const ulonglong2*)&wr[20];
                aA = ffma2(h4.x, w4v.x, aA); aB = ffma2(h4.y, w4v.y, aB);
                aA = ffma2(h5.x, w5v.x, aA); aB = ffma2(h5.y, w5v.y, aB);
                ulonglong2 h6 = *(const ulonglong2*)&hr[24];
                ulonglong2 w6v = *(const ulonglong2*)&wr[24];
                ulonglong2 h7 = *(const ulonglong2*)&hr[28];
                ulonglong2 w7v = *(const ulonglong2*)&wr[28];
                aA = ffma2(h6.x, w6v.x, aA); aB = ffma2(h6.y, w6v.y, aB);
                aA = ffma2(h7.x, w7v.x, aA); aB = ffma2(h7.y, w7v.y, aB);
            }
            u64 s = add2(aA, aB);
            s = add2(s, shfl_xor64(s, 1));   // reduce over kq2 (lane bits 0..1)
            s = add2(s, shfl_xor64(s, 2));
            if (kq2 == 0) {
                float lo, hi; upk2(s, lo, hi);
                float mt = lo + hi + b2v;
                float mu = onema * yreg + alpha * mt;
                float yn = mu + sqa * nz;
                size_t base = ((size_t)(b0r + m2) * TT + t) * DD + d2;
                ys[base]  = yn;
                mts[base] = mt;
                mus[base] = mu;
                yreg = yn;
                sINt[m2 * INP + d2] = yn;
            }
            if (xp) {
                int m = tid - 504;
                *(float4*)&sINt[m * INP + DD] = xn;
            }
        }
        __syncthreads();
    }
}

extern "C" void kernel_launch(void* const* d_in, const int* in_sizes, int n_in,
                              void* d_out, int out_size) {
    const float* carry = (const float*)d_in[0];
    const float* x     = (const float*)d_in[1];
    const float* noise = (const float*)d_in[2];
    const float* W0    = (const float*)d_in[3];
    const float* b0    = (const float*)d_in[4];
    const float* W1    = (const float*)d_in[5];
    const float* b1    = (const float*)d_in[6];
    const float* W2    = (const float*)d_in[7];
    const float* b2    = (const float*)d_in[8];
    float* out = (float*)d_out;

    gnsde_kernel<<<BB / MM, NT>>>(carry, x, noise, W0, b0, W1, b1, W2, b2, out);
}